// round 2
// baseline (speedup 1.0000x reference)
#include <cuda_runtime.h>
#include <math.h>

#define BDIM 4096
#define RDIM 64
#define DDIM 512
#define D4   (DDIM / 4)      // 128 float4 per row
#define BB   32              // batch rows per block
#define NBLOCK (BDIM / BB)   // 128

__device__ float g_partial[NBLOCK];
__device__ int   g_count = 0;

__global__ __launch_bounds__(256, 1)
void fused_kernel(const float* __restrict__ w,
                  const float* __restrict__ e,
                  const float* __restrict__ label,
                  float* __restrict__ out, int out_size)
{
    // s_s[r][b_local]: s = ||e_r||^2 - 2 w.e  (dist^2 minus the per-b constant)
    __shared__ float s_s[RDIM][33];
    __shared__ float red_m1[8][32], red_m2[8][32], red_lm[8][32];
    __shared__ int   red_i1[8][32], red_i2[8][32], red_li[8][32];
    __shared__ float nw_red[BB][9];     // ||w_b||^2 partials, 8 slices per b
    __shared__ int   idx1_s[32];
    __shared__ float fs[NBLOCK];
    __shared__ int   is_last;

    const int tid  = threadIdx.x;
    const int lane = tid & 31;
    const int wid  = tid >> 5;
    const int b0   = blockIdx.x * BB;
    const int r0   = wid * 8;

    const float4* __restrict__ w4 = reinterpret_cast<const float4*>(w)
                                  + (size_t)(b0 + lane) * D4;
    const float4* __restrict__ e4 = reinterpret_cast<const float4*>(e);

    // ---- main loop: pure LDG + FFMA, no smem, no syncs ----
    float acc[8];
#pragma unroll
    for (int j = 0; j < 8; j++) acc[j] = 0.f;

#pragma unroll 2
    for (int d4 = 0; d4 < D4; d4++) {
        float4 wv = w4[d4];                    // own row: L1-resident lines
#pragma unroll
        for (int j = 0; j < 8; j++) {
            float4 ev = e4[(size_t)(r0 + j) * D4 + d4];   // warp-uniform
            acc[j] = fmaf(wv.x, ev.x, acc[j]);
            acc[j] = fmaf(wv.y, ev.y, acc[j]);
            acc[j] = fmaf(wv.z, ev.z, acc[j]);
            acc[j] = fmaf(wv.w, ev.w, acc[j]);
        }
    }

    // ---- ||e_r||^2: lane-sliced within warp (data is L1-hot) ----
    const int sub = lane >> 3;      // d-slice 0..3
    const int rj  = lane & 7;       // relation within warp group
    float ne_part = 0.f;
    {
        const float4* ep = e4 + (size_t)(r0 + rj) * D4 + sub * 32;
#pragma unroll 4
        for (int k = 0; k < 32; k++) {
            float4 v = ep[k];
            ne_part = fmaf(v.x, v.x, ne_part);
            ne_part = fmaf(v.y, v.y, ne_part);
            ne_part = fmaf(v.z, v.z, ne_part);
            ne_part = fmaf(v.w, v.w, ne_part);
        }
    }
    ne_part += __shfl_xor_sync(0xFFFFFFFFu, ne_part, 16);
    ne_part += __shfl_xor_sync(0xFFFFFFFFu, ne_part, 8);
    float ne_j[8];
#pragma unroll
    for (int j = 0; j < 8; j++)
        ne_j[j] = __shfl_sync(0xFFFFFFFFu, ne_part, j);  // lane j -> rel r0+j

    // ---- ||w_b||^2: distributed over all 256 threads (8 slices x 32 b) ----
    {
        const int bl = tid >> 3;           // local b row 0..31
        const int sl = tid & 7;            // d-slice 0..7 (16 float4 each)
        const float4* wp = reinterpret_cast<const float4*>(w)
                         + (size_t)(b0 + bl) * D4 + sl * 16;
        float p = 0.f;
#pragma unroll 4
        for (int k = 0; k < 16; k++) {
            float4 v = wp[k];
            p = fmaf(v.x, v.x, p);
            p = fmaf(v.y, v.y, p);
            p = fmaf(v.z, v.z, p);
            p = fmaf(v.w, v.w, p);
        }
        nw_red[bl][sl] = p;
    }

    // ---- s values + per-warp top-2 (first-index tie-break) ----
    float m1 = -1e30f, m2 = -1e30f;
    int   i1 = r0, i2 = r0;
#pragma unroll
    for (int j = 0; j < 8; j++) {
        float sv = fmaf(-2.f, acc[j], ne_j[j]);
        s_s[r0 + j][lane] = sv;
        if (sv > m1)      { m2 = m1; i2 = i1; m1 = sv; i1 = r0 + j; }
        else if (sv > m2) { m2 = sv; i2 = r0 + j; }
    }

    // ---- label local argmax over this warp's 8 relations ----
    {
        const float* lp = label + (size_t)(b0 + lane) * RDIM + r0;
        float4 la = reinterpret_cast<const float4*>(lp)[0];
        float4 lb = reinterpret_cast<const float4*>(lp)[1];
        float lv[8] = {la.x, la.y, la.z, la.w, lb.x, lb.y, lb.z, lb.w};
        float lm = lv[0]; int li = r0;
#pragma unroll
        for (int j = 1; j < 8; j++)
            if (lv[j] > lm) { lm = lv[j]; li = r0 + j; }
        red_lm[wid][lane] = lm;
        red_li[wid][lane] = li;
    }
    red_m1[wid][lane] = m1;  red_i1[wid][lane] = i1;
    red_m2[wid][lane] = m2;  red_i2[wid][lane] = i2;
    __syncthreads();

    // ---- per-row merge across the 8 warps (warp 0, lane = row) ----
    if (wid == 0) {
        float v1 = red_m1[0][lane]; int ix1 = red_i1[0][lane];
        float v2 = red_m2[0][lane]; int ix2 = red_i2[0][lane];
        float LV = red_lm[0][lane]; int LI  = red_li[0][lane];
#pragma unroll
        for (int g = 1; g < 8; g++) {
            float a1 = red_m1[g][lane]; int aj1 = red_i1[g][lane];
            float a2 = red_m2[g][lane]; int aj2 = red_i2[g][lane];
            if (a1 > v1) {
                if (a2 > v1) { v2 = a2; ix2 = aj2; }
                else         { v2 = v1; ix2 = ix1; }
                v1 = a1; ix1 = aj1;
            } else if (a1 > v2) {
                v2 = a1; ix2 = aj1;
            }
            float al = red_lm[g][lane];
            if (al > LV) { LV = al; LI = red_li[g][lane]; }
        }
        float nw = 0.f;
#pragma unroll
        for (int k = 0; k < 8; k++) nw += nw_red[lane][k];

        const int y = LI;
        float plus2  = fmaxf(nw + s_s[y][lane], 0.f);
        float minus2 = fmaxf(nw + ((ix1 == y) ? v2 : v1), 0.f);
        float loss_b = 1.f + sqrtf(plus2) - sqrtf(minus2);
        idx1_s[lane] = ix1;
        (void)ix2;
#pragma unroll
        for (int off = 16; off; off >>= 1)
            loss_b += __shfl_xor_sync(0xFFFFFFFFu, loss_b, off);
        if (lane == 0) g_partial[blockIdx.x] = loss_b;
    }
    __syncthreads();

    // ---- coalesced one-hot pred write (float4) ----
    {
        float4* op = reinterpret_cast<float4*>(out + (size_t)b0 * RDIM);
#pragma unroll
        for (int k = 0; k < 2; k++) {
            int i  = tid * 8 + k * 4;
            int bl = i >> 6;
            int r  = i & 63;
            int p  = idx1_s[bl];
            float4 v;
            v.x = (r + 0 == p) ? 1.f : 0.f;
            v.y = (r + 1 == p) ? 1.f : 0.f;
            v.z = (r + 2 == p) ? 1.f : 0.f;
            v.w = (r + 3 == p) ? 1.f : 0.f;
            op[tid * 2 + k] = v;
        }
    }

    // ---- fused finalize: last block reduces g_partial deterministically ----
    if (tid == 0) {
        __threadfence();
        int c = atomicAdd(&g_count, 1);
        is_last = (c == gridDim.x - 1) ? 1 : 0;
    }
    __syncthreads();
    if (is_last) {
        __threadfence();   // acquire: make all g_partial writes visible
        if (tid < NBLOCK) fs[tid] = g_partial[tid];
        __syncthreads();
#pragma unroll
        for (int off = NBLOCK / 2; off > 0; off >>= 1) {
            if (tid < off) fs[tid] += fs[tid + off];
            __syncthreads();
        }
        if (tid == 0) {
            out[out_size - 1] = fs[0] * (1.0f / (float)BDIM);
            g_count = 0;   // reset for next graph replay
        }
    }
}

extern "C" void kernel_launch(void* const* d_in, const int* in_sizes, int n_in,
                              void* d_out, int out_size)
{
    const float* w     = (const float*)d_in[0];   // [4096, 512]
    const float* e     = (const float*)d_in[1];   // [64, 512]
    const float* label = (const float*)d_in[2];   // [4096, 64]
    float* out = (float*)d_out;                   // pred [4096*64] ++ loss [1]

    fused_kernel<<<NBLOCK, 256>>>(w, e, label, out, out_size);
}

// round 3
// speedup vs baseline: 1.8137x; 1.8137x over previous
#include <cuda_runtime.h>
#include <math.h>

#define BDIM 4096
#define RDIM 64
#define DDIM 512
#define BB   32               // batch rows per block
#define DC   32               // d-chunk per stage
#define NCHUNK (DDIM / DC)    // 16
#define WPAD 36               // padded row stride (floats) for w/e tiles
#define NBLOCK (BDIM / BB)    // 128

__device__ float g_partial[NBLOCK];
__device__ int   g_count = 0;

__device__ __forceinline__ void cp16(void* smem_dst, const void* gmem_src) {
    unsigned s = (unsigned)__cvta_generic_to_shared(smem_dst);
    asm volatile("cp.async.ca.shared.global [%0], [%1], 16;\n" :: "r"(s), "l"(gmem_src));
}
#define CP_COMMIT()  asm volatile("cp.async.commit_group;\n" ::: "memory")
#define CP_WAIT(n)   asm volatile("cp.async.wait_group %0;\n" :: "n"(n) : "memory")

// packed f32x2 fma: both halves get independent fma — 2 FMAs per instruction
__device__ __forceinline__ double ffma2(double a, double b, double c) {
    double d;
    asm("fma.rn.f32x2 %0, %1, %2, %3;" : "=d"(d) : "d"(a), "d"(b), "d"(c));
    return d;
}

__global__ __launch_bounds__(256, 1)
void fused_kernel(const float* __restrict__ w,
                  const float* __restrict__ e,
                  const float* __restrict__ label,
                  float* __restrict__ out, int out_size)
{
    // double-buffered tiles (16B-aligned rows: 36 floats = 144B = 9*16B)
    __shared__ __align__(16) float w_s[2][BB * WPAD];     // 9.2 KB
    __shared__ __align__(16) float e_s[2][RDIM * WPAD];   // 18.4 KB
    // epilogue scratch
    __shared__ float s_s[RDIM][33];
    __shared__ float red_m1[8][32], red_m2[8][32], red_lm[8][32];
    __shared__ int   red_i1[8][32], red_i2[8][32], red_li[8][32];
    __shared__ float nw_red[BB][9];
    __shared__ int   idx1_s[32];
    __shared__ float fs[NBLOCK];
    __shared__ int   is_last;

    const int tid  = threadIdx.x;
    const int lane = tid & 31;
    const int wid  = tid >> 5;
    const int b0   = blockIdx.x * BB;
    const int r0   = wid * 8;

    // ---- staging: exactly 1 w cp.async + 2 e cp.async per thread per chunk
    const int s_bl  = tid >> 3;          // w row 0..31
    const int s_f4  = (tid & 7) * 4;     // float offset within chunk
    const float* wg = w + (size_t)(b0 + s_bl) * DDIM + s_f4;
    const int s_r0  = tid >> 3;          // e rows: tid>>3 and (tid+256)>>3
    const float* eg = e + s_f4;

    // prefetch chunk 0
    {
        cp16(&w_s[0][s_bl * WPAD + s_f4], wg);
        cp16(&e_s[0][s_r0 * WPAD + s_f4],        eg + (size_t)s_r0 * DDIM);
        cp16(&e_s[0][(s_r0 + 32) * WPAD + s_f4], eg + (size_t)(s_r0 + 32) * DDIM);
        CP_COMMIT();
    }

    double acc[8];
#pragma unroll
    for (int j = 0; j < 8; j++) acc[j] = 0.0;

    for (int c = 0; c < NCHUNK; c++) {
        const int buf = c & 1;
        if (c + 1 < NCHUNK) {
            const int d0 = (c + 1) * DC;
            const int nb = buf ^ 1;
            cp16(&w_s[nb][s_bl * WPAD + s_f4], wg + d0);
            cp16(&e_s[nb][s_r0 * WPAD + s_f4],        eg + (size_t)s_r0 * DDIM + d0);
            cp16(&e_s[nb][(s_r0 + 32) * WPAD + s_f4], eg + (size_t)(s_r0 + 32) * DDIM + d0);
            CP_COMMIT();
            CP_WAIT(1);          // chunk c has landed
        } else {
            CP_WAIT(0);
        }
        __syncthreads();

        const float* wrow = &w_s[buf][lane * WPAD];
        const float* erow = &e_s[buf][r0 * WPAD];
#pragma unroll
        for (int it = 0; it < DC / 4; it++) {
            const int d = it * 4;
            double2 wv = *reinterpret_cast<const double2*>(wrow + d);  // 4 w floats
#pragma unroll
            for (int j = 0; j < 8; j++) {
                double2 ev = *reinterpret_cast<const double2*>(erow + j * WPAD + d);
                acc[j] = ffma2(wv.x, ev.x, acc[j]);
                acc[j] = ffma2(wv.y, ev.y, acc[j]);
            }
        }
        __syncthreads();
    }

    // ---- ||e_r||^2: lane-sliced within warp (L2-hot global reads, once) ----
    const int sub = lane >> 3;
    const int rj  = lane & 7;
    const float4* e4 = reinterpret_cast<const float4*>(e);
    float ne_part = 0.f;
    {
        const float4* ep = e4 + (size_t)(r0 + rj) * (DDIM / 4) + sub * 32;
#pragma unroll 4
        for (int k = 0; k < 32; k++) {
            float4 v = ep[k];
            ne_part = fmaf(v.x, v.x, ne_part);
            ne_part = fmaf(v.y, v.y, ne_part);
            ne_part = fmaf(v.z, v.z, ne_part);
            ne_part = fmaf(v.w, v.w, ne_part);
        }
    }
    ne_part += __shfl_xor_sync(0xFFFFFFFFu, ne_part, 16);
    ne_part += __shfl_xor_sync(0xFFFFFFFFu, ne_part, 8);
    float ne_j[8];
#pragma unroll
    for (int j = 0; j < 8; j++)
        ne_j[j] = __shfl_sync(0xFFFFFFFFu, ne_part, j);

    // ---- ||w_b||^2: distributed over 256 threads ----
    {
        const int bl = tid >> 3;
        const int sl = tid & 7;
        const float4* wp = reinterpret_cast<const float4*>(w)
                         + (size_t)(b0 + bl) * (DDIM / 4) + sl * 16;
        float p = 0.f;
#pragma unroll 4
        for (int k = 0; k < 16; k++) {
            float4 v = wp[k];
            p = fmaf(v.x, v.x, p);
            p = fmaf(v.y, v.y, p);
            p = fmaf(v.z, v.z, p);
            p = fmaf(v.w, v.w, p);
        }
        nw_red[bl][sl] = p;
    }

    // ---- s = ||e||^2 - 2 w.e ; per-warp top-2 (first-index tie-break) ----
    float m1 = -1e30f, m2 = -1e30f;
    int   i1 = r0, i2 = r0;
#pragma unroll
    for (int j = 0; j < 8; j++) {
        float2 h = *reinterpret_cast<float2*>(&acc[j]);
        float dot = h.x + h.y;
        float sv = fmaf(-2.f, dot, ne_j[j]);
        s_s[r0 + j][lane] = sv;
        if (sv > m1)      { m2 = m1; i2 = i1; m1 = sv; i1 = r0 + j; }
        else if (sv > m2) { m2 = sv; i2 = r0 + j; }
    }

    // ---- label argmax over this warp's 8 relations ----
    {
        const float* lp = label + (size_t)(b0 + lane) * RDIM + r0;
        float4 la = reinterpret_cast<const float4*>(lp)[0];
        float4 lb = reinterpret_cast<const float4*>(lp)[1];
        float lv[8] = {la.x, la.y, la.z, la.w, lb.x, lb.y, lb.z, lb.w};
        float lm = lv[0]; int li = r0;
#pragma unroll
        for (int j = 1; j < 8; j++)
            if (lv[j] > lm) { lm = lv[j]; li = r0 + j; }
        red_lm[wid][lane] = lm;
        red_li[wid][lane] = li;
    }
    red_m1[wid][lane] = m1;  red_i1[wid][lane] = i1;
    red_m2[wid][lane] = m2;  red_i2[wid][lane] = i2;
    __syncthreads();

    // ---- per-row merge across the 8 warps (warp 0, lane = row) ----
    if (wid == 0) {
        float v1 = red_m1[0][lane]; int ix1 = red_i1[0][lane];
        float v2 = red_m2[0][lane]; int ix2 = red_i2[0][lane];
        float LV = red_lm[0][lane]; int LI  = red_li[0][lane];
#pragma unroll
        for (int g = 1; g < 8; g++) {
            float a1 = red_m1[g][lane]; int aj1 = red_i1[g][lane];
            float a2 = red_m2[g][lane]; int aj2 = red_i2[g][lane];
            if (a1 > v1) {
                if (a2 > v1) { v2 = a2; ix2 = aj2; }
                else         { v2 = v1; ix2 = ix1; }
                v1 = a1; ix1 = aj1;
            } else if (a1 > v2) {
                v2 = a1; ix2 = aj1;
            }
            float al = red_lm[g][lane];
            if (al > LV) { LV = al; LI = red_li[g][lane]; }
        }
        float nw = 0.f;
#pragma unroll
        for (int k = 0; k < 8; k++) nw += nw_red[lane][k];

        const int y = LI;
        float plus2  = fmaxf(nw + s_s[y][lane], 0.f);
        float minus2 = fmaxf(nw + ((ix1 == y) ? v2 : v1), 0.f);
        float loss_b = 1.f + sqrtf(plus2) - sqrtf(minus2);
        idx1_s[lane] = ix1;
        (void)ix2;
#pragma unroll
        for (int off = 16; off; off >>= 1)
            loss_b += __shfl_xor_sync(0xFFFFFFFFu, loss_b, off);
        if (lane == 0) g_partial[blockIdx.x] = loss_b;
    }
    __syncthreads();

    // ---- coalesced one-hot pred write (float4) ----
    {
        float4* op = reinterpret_cast<float4*>(out + (size_t)b0 * RDIM);
#pragma unroll
        for (int k = 0; k < 2; k++) {
            int i  = tid * 8 + k * 4;
            int bl = i >> 6;
            int r  = i & 63;
            int p  = idx1_s[bl];
            float4 v;
            v.x = (r + 0 == p) ? 1.f : 0.f;
            v.y = (r + 1 == p) ? 1.f : 0.f;
            v.z = (r + 2 == p) ? 1.f : 0.f;
            v.w = (r + 3 == p) ? 1.f : 0.f;
            op[tid * 2 + k] = v;
        }
    }

    // ---- fused finalize: last block reduces g_partial deterministically ----
    if (tid == 0) {
        __threadfence();
        int c = atomicAdd(&g_count, 1);
        is_last = (c == gridDim.x - 1) ? 1 : 0;
    }
    __syncthreads();
    if (is_last) {
        __threadfence();
        if (tid < NBLOCK) fs[tid] = g_partial[tid];
        __syncthreads();
#pragma unroll
        for (int off = NBLOCK / 2; off > 0; off >>= 1) {
            if (tid < off) fs[tid] += fs[tid + off];
            __syncthreads();
        }
        if (tid == 0) {
            out[out_size - 1] = fs[0] * (1.0f / (float)BDIM);
            g_count = 0;
        }
    }
}

extern "C" void kernel_launch(void* const* d_in, const int* in_sizes, int n_in,
                              void* d_out, int out_size)
{
    const float* w     = (const float*)d_in[0];   // [4096, 512]
    const float* e     = (const float*)d_in[1];   // [64, 512]
    const float* label = (const float*)d_in[2];   // [4096, 64]
    float* out = (float*)d_out;                   // pred [4096*64] ++ loss [1]

    fused_kernel<<<NBLOCK, 256>>>(w, e, label, out, out_size);
}

// round 4
// speedup vs baseline: 2.1126x; 1.1648x over previous
#include <cuda_runtime.h>
#include <math.h>
#include <stdint.h>

#define BDIM 4096
#define RDIM 64
#define DDIM 512
#define BB   32
#define NBLOCK (BDIM / BB)     // 128
#define ROWF 516               // padded row stride (floats): 516 mod 32 == 4
#define W_TILE_F (BB * ROWF)   // 16512
#define E_TILE_F (RDIM * ROWF) // 33024
#define DYN_SMEM ((W_TILE_F + E_TILE_F) * 4)   // 198144 B

__device__ float g_partial[NBLOCK];
__device__ int   g_count = 0;

__device__ __forceinline__ uint32_t smem_u32(const void* p) {
    return (uint32_t)__cvta_generic_to_shared(p);
}
__device__ __forceinline__ void bulk_cp(uint32_t dst, const void* src,
                                        uint32_t bytes, uint32_t mbar) {
    asm volatile(
        "cp.async.bulk.shared::cta.global.mbarrier::complete_tx::bytes [%0], [%1], %2, [%3];"
        :: "r"(dst), "l"(src), "r"(bytes), "r"(mbar) : "memory");
}
__device__ __forceinline__ void mbar_init(uint32_t mbar, uint32_t cnt) {
    asm volatile("mbarrier.init.shared.b64 [%0], %1;" :: "r"(mbar), "r"(cnt) : "memory");
}
__device__ __forceinline__ void mbar_expect_tx(uint32_t mbar, uint32_t bytes) {
    asm volatile("mbarrier.arrive.expect_tx.shared.b64 _, [%0], %1;"
                 :: "r"(mbar), "r"(bytes) : "memory");
}
__device__ __forceinline__ void mbar_wait(uint32_t mbar, uint32_t parity) {
    asm volatile(
        "{\n\t.reg .pred P;\n\t"
        "WL_%=:\n\t"
        "mbarrier.try_wait.parity.acquire.cta.shared::cta.b64 P, [%0], %1, 0x989680;\n\t"
        "@P bra.uni WD_%=;\n\t"
        "bra.uni WL_%=;\n\t"
        "WD_%=:\n\t}"
        :: "r"(mbar), "r"(parity) : "memory");
}
// packed f32x2 fma: two independent fp32 FMAs per instruction
__device__ __forceinline__ double ffma2(double a, double b, double c) {
    double d;
    asm("fma.rn.f32x2 %0, %1, %2, %3;" : "=d"(d) : "d"(a), "d"(b), "d"(c));
    return d;
}

__global__ __launch_bounds__(256, 1)
void fused_kernel(const float* __restrict__ w,
                  const float* __restrict__ e,
                  const float* __restrict__ label,
                  float* __restrict__ out, int out_size)
{
    extern __shared__ __align__(16) float dyn[];
    float* w_s = dyn;                 // [BB][ROWF]
    float* e_s = dyn + W_TILE_F;      // [RDIM][ROWF]

    __shared__ __align__(8) uint64_t mbar_storage;
    __shared__ float ne_red[RDIM][4];
    __shared__ float ne_s[RDIM];
    __shared__ float nw_red[BB][9];
    __shared__ float s_s[RDIM][33];
    __shared__ float red_m1[8][32], red_m2[8][32], red_lm[8][32];
    __shared__ int   red_i1[8][32], red_i2[8][32], red_li[8][32];
    __shared__ int   idx1_s[32];
    __shared__ float fs[NBLOCK];
    __shared__ int   is_last;

    const int tid  = threadIdx.x;
    const int lane = tid & 31;
    const int wid  = tid >> 5;
    const int b0   = blockIdx.x * BB;
    const uint32_t mbar = smem_u32(&mbar_storage);

    // ---- stage entire w tile (32 rows) + entire e (64 rows) via bulk async copy
    if (tid == 0) mbar_init(mbar, 1);
    __syncthreads();
    if (tid == 0) mbar_expect_tx(mbar, (BB + RDIM) * DDIM * 4);
    __syncthreads();
    if (tid < BB) {
        bulk_cp(smem_u32(w_s + tid * ROWF),
                w + (size_t)(b0 + tid) * DDIM, DDIM * 4, mbar);
    } else if (tid < BB + RDIM) {
        int r = tid - BB;
        bulk_cp(smem_u32(e_s + r * ROWF),
                e + (size_t)r * DDIM, DDIM * 4, mbar);
    }
    mbar_wait(mbar, 0);

    // ---- ||e_r||^2 partials: thread -> (r = tid>>2, slice = tid&3), 32 float4 each
    {
        const int r = tid >> 2, sl = tid & 3;
        const float4* p = reinterpret_cast<const float4*>(e_s + r * ROWF + sl * 128);
        float a = 0.f;
#pragma unroll 8
        for (int k = 0; k < 32; k++) {
            float4 v = p[k];
            a = fmaf(v.x, v.x, a); a = fmaf(v.y, v.y, a);
            a = fmaf(v.z, v.z, a); a = fmaf(v.w, v.w, a);
        }
        ne_red[r][sl] = a;
    }
    // ---- ||w_b||^2 partials: (bl = tid>>3, slice = tid&7), 16 float4 each
    {
        const int bl = tid >> 3, sl = tid & 7;
        const float4* p = reinterpret_cast<const float4*>(w_s + bl * ROWF + sl * 64);
        float a = 0.f;
#pragma unroll 4
        for (int k = 0; k < 16; k++) {
            float4 v = p[k];
            a = fmaf(v.x, v.x, a); a = fmaf(v.y, v.y, a);
            a = fmaf(v.z, v.z, a); a = fmaf(v.w, v.w, a);
        }
        nw_red[bl][sl] = a;
    }
    __syncthreads();
    if (tid < RDIM)
        ne_s[tid] = ne_red[tid][0] + ne_red[tid][1] + ne_red[tid][2] + ne_red[tid][3];
    __syncthreads();

    // ---- main loop: register tile 4b x 2r per thread, zero barriers ----
    const int bg  = lane >> 2;      // 0..7   (b = bg + 8k)
    const int rg  = lane & 3;       // 0..3   (r = r0w + rg + 4m)
    const int r0w = wid * 8;
    const float* wp0 = w_s + bg * ROWF;
    const float* ep0 = e_s + (r0w + rg) * ROWF;

    double acc[4][2];
#pragma unroll
    for (int k = 0; k < 4; k++)
#pragma unroll
        for (int m = 0; m < 2; m++) acc[k][m] = 0.0;

#pragma unroll 4
    for (int g = 0; g < DDIM / 4; g++) {
        const int d = g * 4;
        float4 wf[4], ef[2];
#pragma unroll
        for (int k = 0; k < 4; k++)
            wf[k] = *reinterpret_cast<const float4*>(wp0 + k * 8 * ROWF + d);
#pragma unroll
        for (int m = 0; m < 2; m++)
            ef[m] = *reinterpret_cast<const float4*>(ep0 + m * 4 * ROWF + d);
#pragma unroll
        for (int k = 0; k < 4; k++) {
            double2 wd = *reinterpret_cast<double2*>(&wf[k]);
#pragma unroll
            for (int m = 0; m < 2; m++) {
                double2 ed = *reinterpret_cast<double2*>(&ef[m]);
                acc[k][m] = ffma2(wd.x, ed.x, acc[k][m]);
                acc[k][m] = ffma2(wd.y, ed.y, acc[k][m]);
            }
        }
    }

    // ---- s = ||e||^2 - 2 w.e into s_s[r][b] ----
#pragma unroll
    for (int k = 0; k < 4; k++) {
#pragma unroll
        for (int m = 0; m < 2; m++) {
            float2 h = *reinterpret_cast<float2*>(&acc[k][m]);
            float dot = h.x + h.y;
            int r = r0w + rg + 4 * m;
            int b = bg + 8 * k;
            s_s[r][b] = fmaf(-2.f, dot, ne_s[r]);
        }
    }
    __syncthreads();

    // ---- per-warp top-2 over its 8 relations (lane = b, first-index ties) ----
    float m1 = -1e30f, m2 = -1e30f;
    int   i1 = r0w, i2 = r0w;
#pragma unroll
    for (int j = 0; j < 8; j++) {
        float sv = s_s[r0w + j][lane];
        if (sv > m1)      { m2 = m1; i2 = i1; m1 = sv; i1 = r0w + j; }
        else if (sv > m2) { m2 = sv; i2 = r0w + j; }
    }
    // ---- label local argmax over this warp's 8 relations ----
    {
        const float* lp = label + (size_t)(b0 + lane) * RDIM + r0w;
        float4 la = reinterpret_cast<const float4*>(lp)[0];
        float4 lb = reinterpret_cast<const float4*>(lp)[1];
        float lv[8] = {la.x, la.y, la.z, la.w, lb.x, lb.y, lb.z, lb.w};
        float lm = lv[0]; int li = r0w;
#pragma unroll
        for (int j = 1; j < 8; j++)
            if (lv[j] > lm) { lm = lv[j]; li = r0w + j; }
        red_lm[wid][lane] = lm;
        red_li[wid][lane] = li;
    }
    red_m1[wid][lane] = m1;  red_i1[wid][lane] = i1;
    red_m2[wid][lane] = m2;  red_i2[wid][lane] = i2;
    __syncthreads();

    // ---- per-row merge across the 8 warps (warp 0, lane = row) ----
    if (wid == 0) {
        float v1 = red_m1[0][lane]; int ix1 = red_i1[0][lane];
        float v2 = red_m2[0][lane]; int ix2 = red_i2[0][lane];
        float LV = red_lm[0][lane]; int LI  = red_li[0][lane];
#pragma unroll
        for (int g = 1; g < 8; g++) {
            float a1 = red_m1[g][lane]; int aj1 = red_i1[g][lane];
            float a2 = red_m2[g][lane]; int aj2 = red_i2[g][lane];
            if (a1 > v1) {
                if (a2 > v1) { v2 = a2; ix2 = aj2; }
                else         { v2 = v1; ix2 = ix1; }
                v1 = a1; ix1 = aj1;
            } else if (a1 > v2) {
                v2 = a1; ix2 = aj1;
            }
            float al = red_lm[g][lane];
            if (al > LV) { LV = al; LI = red_li[g][lane]; }
        }
        float nw = 0.f;
#pragma unroll
        for (int k = 0; k < 8; k++) nw += nw_red[lane][k];

        const int y = LI;
        float plus2  = fmaxf(nw + s_s[y][lane], 0.f);
        float minus2 = fmaxf(nw + ((ix1 == y) ? v2 : v1), 0.f);
        float loss_b = 1.f + sqrtf(plus2) - sqrtf(minus2);
        idx1_s[lane] = ix1;
        (void)ix2;
#pragma unroll
        for (int off = 16; off; off >>= 1)
            loss_b += __shfl_xor_sync(0xFFFFFFFFu, loss_b, off);
        if (lane == 0) g_partial[blockIdx.x] = loss_b;
    }
    __syncthreads();

    // ---- coalesced one-hot pred write (float4) ----
    {
        float4* op = reinterpret_cast<float4*>(out + (size_t)b0 * RDIM);
#pragma unroll
        for (int k = 0; k < 2; k++) {
            int i  = tid * 8 + k * 4;
            int bl = i >> 6;
            int r  = i & 63;
            int p  = idx1_s[bl];
            float4 v;
            v.x = (r + 0 == p) ? 1.f : 0.f;
            v.y = (r + 1 == p) ? 1.f : 0.f;
            v.z = (r + 2 == p) ? 1.f : 0.f;
            v.w = (r + 3 == p) ? 1.f : 0.f;
            op[tid * 2 + k] = v;
        }
    }

    // ---- fused finalize: last block reduces g_partial deterministically ----
    if (tid == 0) {
        __threadfence();
        int c = atomicAdd(&g_count, 1);
        is_last = (c == gridDim.x - 1) ? 1 : 0;
    }
    __syncthreads();
    if (is_last) {
        __threadfence();
        if (tid < NBLOCK) fs[tid] = g_partial[tid];
        __syncthreads();
#pragma unroll
        for (int off = NBLOCK / 2; off > 0; off >>= 1) {
            if (tid < off) fs[tid] += fs[tid + off];
            __syncthreads();
        }
        if (tid == 0) {
            out[out_size - 1] = fs[0] * (1.0f / (float)BDIM);
            g_count = 0;
        }
    }
}

extern "C" void kernel_launch(void* const* d_in, const int* in_sizes, int n_in,
                              void* d_out, int out_size)
{
    const float* w     = (const float*)d_in[0];   // [4096, 512]
    const float* e     = (const float*)d_in[1];   // [64, 512]
    const float* label = (const float*)d_in[2];   // [4096, 64]
    float* out = (float*)d_out;                   // pred [4096*64] ++ loss [1]

    cudaFuncSetAttribute(fused_kernel,
                         cudaFuncAttributeMaxDynamicSharedMemorySize, DYN_SMEM);
    fused_kernel<<<NBLOCK, 256, DYN_SMEM>>>(w, e, label, out, out_size);
}